// round 3
// baseline (speedup 1.0000x reference)
#include <cuda_runtime.h>
#include <cstdint>

#define HID 128
#define NMAX 100000
#define EMAX 1600000
#define SCAN_B 1024

// ---------------- static scratch (no allocation allowed) ----------------
__device__ int   g_is64;                            // edge_index dtype flag
__device__ float g_dis[NMAX];                       // deg^{-1/2} (self-looped degree)
__device__ int   g_cnt[NMAX];                       // in-degree (w/o self loop)
__device__ int   g_rowstart[NMAX];                  // CSR row starts (exclusive scan of cnt)
__device__ int   g_cursor[NMAX];                    // fill cursors
__device__ int   g_bsum[SCAN_B];                    // scan block sums
__device__ int   g_csr_src[EMAX];                   // CSR: source node per slot
__device__ float g_csr_nrm[EMAX];                   // CSR: edge norm per slot
__device__ float g_t[(size_t)NMAX * HID];           // per-layer GEMM output (pre-aggregation)
__device__ float g_h[(size_t)NMAX * HID];           // aggregated hidden state
__device__ float g_t5[(size_t)NMAX * 3];            // last-layer GEMM output

// ---------------- edge dtype probe ----------------
// If edge_index is int64 (values in [0, N), non-negative, little-endian) every
// odd 32-bit word is 0. If int32, odd words are random node ids (~never all 0).
__global__ void k_probe(const int* __restrict__ ei32, int E) {
    if (blockIdx.x == 0 && threadIdx.x == 0) {
        int allz = 1;
        int stride = (2 * E) / 64;
        for (int i = 0; i < 64; i++) {
            int idx = (i * stride) | 1;          // odd index, < 2E
            if (ei32[idx] != 0) { allz = 0; break; }
        }
        g_is64 = allz;
    }
}

__device__ __forceinline__ int edge_at(const void* ei, int is64, size_t idx) {
    if (is64) return (int)((const long long*)ei)[idx];
    return ((const int*)ei)[idx];
}

// ---------------- CSR construction ----------------
__global__ void k_zero2(int* __restrict__ a, int* __restrict__ b, int n) {
    int i = blockIdx.x * blockDim.x + threadIdx.x;
    if (i < n) { a[i] = 0; b[i] = 0; }
}

__global__ void k_hist(const void* __restrict__ ei, int* __restrict__ cnt, int E) {
    int e = blockIdx.x * blockDim.x + threadIdx.x;
    if (e < E) {
        int d = edge_at(ei, g_is64, (size_t)E + e);
        atomicAdd(&cnt[d], 1);
    }
}

__global__ void k_dis(const int* __restrict__ cnt, float* __restrict__ dis, int n) {
    int i = blockIdx.x * blockDim.x + threadIdx.x;
    if (i < n) dis[i] = rsqrtf((float)cnt[i] + 1.0f);   // +1 self loop
}

__global__ __launch_bounds__(SCAN_B) void k_scan_block(
    const int* __restrict__ cnt, int* __restrict__ out, int* __restrict__ bsum, int n)
{
    __shared__ int sh[SCAN_B];
    int i = blockIdx.x * SCAN_B + threadIdx.x;
    int v = (i < n) ? cnt[i] : 0;
    sh[threadIdx.x] = v;
    __syncthreads();
#pragma unroll
    for (int off = 1; off < SCAN_B; off <<= 1) {
        int t = (threadIdx.x >= off) ? sh[threadIdx.x - off] : 0;
        __syncthreads();
        sh[threadIdx.x] += t;
        __syncthreads();
    }
    if (i < n) out[i] = sh[threadIdx.x] - v;                // exclusive
    if (threadIdx.x == SCAN_B - 1) bsum[blockIdx.x] = sh[SCAN_B - 1];
}

__global__ __launch_bounds__(SCAN_B) void k_scan_top(int* __restrict__ bsum, int nb) {
    __shared__ int sh[SCAN_B];
    int v = (threadIdx.x < nb) ? bsum[threadIdx.x] : 0;
    sh[threadIdx.x] = v;
    __syncthreads();
#pragma unroll
    for (int off = 1; off < SCAN_B; off <<= 1) {
        int t = (threadIdx.x >= off) ? sh[threadIdx.x - off] : 0;
        __syncthreads();
        sh[threadIdx.x] += t;
        __syncthreads();
    }
    if (threadIdx.x < nb) bsum[threadIdx.x] = sh[threadIdx.x] - v;  // exclusive
}

__global__ void k_scan_add(int* __restrict__ out, const int* __restrict__ bsum, int n) {
    int i = blockIdx.x * SCAN_B + threadIdx.x;
    if (i < n) out[i] += bsum[blockIdx.x];
}

__global__ void k_fill_csr(const void* __restrict__ ei,
                           const int* __restrict__ rowstart, int* __restrict__ cursor,
                           const float* __restrict__ dis,
                           int* __restrict__ csrc, float* __restrict__ cnrm, int E)
{
    int e = blockIdx.x * blockDim.x + threadIdx.x;
    if (e >= E) return;
    int is64 = g_is64;
    int s = edge_at(ei, is64, e);
    int d = edge_at(ei, is64, (size_t)E + e);
    int pos = rowstart[d] + atomicAdd(&cursor[d], 1);
    csrc[pos] = s;
    cnrm[pos] = dis[s] * dis[d];
}

// ---------------- SGEMM: C[N,128] = act(A[N,K]) @ B[K,128] ----------------
// BM=64, BN=128(full), BK=16; 256 threads; 8x4 microtile per thread.
__global__ __launch_bounds__(256) void k_sgemm128(
    const float* __restrict__ A, const float* __restrict__ B,
    float* __restrict__ C, int Nrows, int K, int doRelu)
{
    const int BM = 64, BK = 16;
    __shared__ float As[BK][BM];      // transposed: As[k][m]
    __shared__ float Bs[BK][HID];

    int tid = threadIdx.x;
    int tr  = tid >> 5;               // 0..7  (row group, 8 rows each)
    int tc  = tid & 31;               // 0..31 (col group, 4 cols each)
    int row0 = blockIdx.x * BM;

    float acc[8][4];
#pragma unroll
    for (int i = 0; i < 8; i++)
#pragma unroll
        for (int j = 0; j < 4; j++) acc[i][j] = 0.f;

    for (int k0 = 0; k0 < K; k0 += BK) {
        // ---- load A tile: 64x16, 4 elems/thread ----
        {
            int id = tid * 4;
            int r  = id >> 4;          // 0..63
            int kk = id & 15;          // 0,4,8,12
            int grow = row0 + r;
            if (grow < Nrows && (k0 + BK) <= K) {
                float4 v = *reinterpret_cast<const float4*>(A + (size_t)grow * K + k0 + kk);
                if (doRelu) { v.x = fmaxf(v.x, 0.f); v.y = fmaxf(v.y, 0.f);
                              v.z = fmaxf(v.z, 0.f); v.w = fmaxf(v.w, 0.f); }
                As[kk + 0][r] = v.x; As[kk + 1][r] = v.y;
                As[kk + 2][r] = v.z; As[kk + 3][r] = v.w;
            } else {
#pragma unroll
                for (int j = 0; j < 4; j++) {
                    int gk = k0 + kk + j;
                    float v = (grow < Nrows && gk < K) ? A[(size_t)grow * K + gk] : 0.f;
                    if (doRelu) v = fmaxf(v, 0.f);
                    As[kk + j][r] = v;
                }
            }
        }
        // ---- load B tile: 16x128, 2 float4/thread ----
#pragma unroll
        for (int hh = 0; hh < 2; hh++) {
            int elem = (tid * 2 + hh) * 4;     // 0..2044
            int br = elem >> 7;                // k-row 0..15
            int bc = elem & 127;
            int gk = k0 + br;
            float4 v = make_float4(0.f, 0.f, 0.f, 0.f);
            if (gk < K) v = *reinterpret_cast<const float4*>(B + (size_t)gk * HID + bc);
            *reinterpret_cast<float4*>(&Bs[br][bc]) = v;
        }
        __syncthreads();

#pragma unroll
        for (int kk = 0; kk < BK; kk++) {
            float4 a0 = *reinterpret_cast<const float4*>(&As[kk][tr * 8]);
            float4 a1 = *reinterpret_cast<const float4*>(&As[kk][tr * 8 + 4]);
            float4 bv = *reinterpret_cast<const float4*>(&Bs[kk][tc * 4]);
            float ra[8] = {a0.x, a0.y, a0.z, a0.w, a1.x, a1.y, a1.z, a1.w};
            float rb[4] = {bv.x, bv.y, bv.z, bv.w};
#pragma unroll
            for (int i = 0; i < 8; i++)
#pragma unroll
                for (int j = 0; j < 4; j++)
                    acc[i][j] += ra[i] * rb[j];
        }
        __syncthreads();
    }

#pragma unroll
    for (int i = 0; i < 8; i++) {
        int grow = row0 + tr * 8 + i;
        if (grow < Nrows) {
            float4 v = make_float4(acc[i][0], acc[i][1], acc[i][2], acc[i][3]);
            *reinterpret_cast<float4*>(C + (size_t)grow * HID + tc * 4) = v;
        }
    }
}

// ---------------- gather aggregation: one warp per dst node ----------------
// O[n,:] = sum_{s in nbr(n)} T[s,:]*norm + T[n,:]*dis[n]^2 + bias
__global__ void k_gather128(const float* __restrict__ T,
                            const int* __restrict__ rowstart, const int* __restrict__ cnt,
                            const int* __restrict__ csrc, const float* __restrict__ cnrm,
                            const float* __restrict__ dis, const float* __restrict__ bias,
                            float* __restrict__ O, int Nn)
{
    int g = blockIdx.x * blockDim.x + threadIdx.x;
    int n = g >> 5;
    int lane = g & 31;
    if (n >= Nn) return;
    int base = rowstart[n];
    int deg  = cnt[n];

    float ax = 0.f, ay = 0.f, az = 0.f, aw = 0.f;
    int j = 0;
    for (; j + 2 <= deg; j += 2) {
        int   s0 = __ldg(csrc + base + j);
        int   s1 = __ldg(csrc + base + j + 1);
        float n0 = __ldg(cnrm + base + j);
        float n1 = __ldg(cnrm + base + j + 1);
        float4 v0 = __ldg(reinterpret_cast<const float4*>(T + (size_t)s0 * HID) + lane);
        float4 v1 = __ldg(reinterpret_cast<const float4*>(T + (size_t)s1 * HID) + lane);
        ax += v0.x * n0; ay += v0.y * n0; az += v0.z * n0; aw += v0.w * n0;
        ax += v1.x * n1; ay += v1.y * n1; az += v1.z * n1; aw += v1.w * n1;
    }
    if (j < deg) {
        int   s0 = __ldg(csrc + base + j);
        float n0 = __ldg(cnrm + base + j);
        float4 v0 = __ldg(reinterpret_cast<const float4*>(T + (size_t)s0 * HID) + lane);
        ax += v0.x * n0; ay += v0.y * n0; az += v0.z * n0; aw += v0.w * n0;
    }

    float d2 = dis[n]; d2 *= d2;
    float4 t = reinterpret_cast<const float4*>(T + (size_t)n * HID)[lane];
    float4 b = reinterpret_cast<const float4*>(bias)[lane];
    float4 o = make_float4(ax + t.x * d2 + b.x, ay + t.y * d2 + b.y,
                           az + t.z * d2 + b.z, aw + t.w * d2 + b.w);
    reinterpret_cast<float4*>(O + (size_t)n * HID)[lane] = o;
}

// ---------------- last layer: T5[N,3] = relu(H[N,128]) @ W5[128,3], warp per row ----------------
__global__ void k_gemm3(const float* __restrict__ Hm, const float* __restrict__ W,
                        float* __restrict__ T5, int Nn)
{
    __shared__ float Ws[HID * 3];
    for (int i = threadIdx.x; i < HID * 3; i += blockDim.x) Ws[i] = W[i];
    __syncthreads();

    int g = blockIdx.x * blockDim.x + threadIdx.x;
    int row = g >> 5;
    int lane = g & 31;
    if (row >= Nn) return;

    float4 v = *reinterpret_cast<const float4*>(Hm + (size_t)row * HID + lane * 4);
    int k = lane * 4;
    float a0 = 0.f, a1 = 0.f, a2 = 0.f, hv;
    hv = fmaxf(v.x, 0.f); a0 += hv * Ws[(k + 0) * 3 + 0]; a1 += hv * Ws[(k + 0) * 3 + 1]; a2 += hv * Ws[(k + 0) * 3 + 2];
    hv = fmaxf(v.y, 0.f); a0 += hv * Ws[(k + 1) * 3 + 0]; a1 += hv * Ws[(k + 1) * 3 + 1]; a2 += hv * Ws[(k + 1) * 3 + 2];
    hv = fmaxf(v.z, 0.f); a0 += hv * Ws[(k + 2) * 3 + 0]; a1 += hv * Ws[(k + 2) * 3 + 1]; a2 += hv * Ws[(k + 2) * 3 + 2];
    hv = fmaxf(v.w, 0.f); a0 += hv * Ws[(k + 3) * 3 + 0]; a1 += hv * Ws[(k + 3) * 3 + 1]; a2 += hv * Ws[(k + 3) * 3 + 2];

#pragma unroll
    for (int off = 16; off > 0; off >>= 1) {
        a0 += __shfl_down_sync(0xffffffffu, a0, off);
        a1 += __shfl_down_sync(0xffffffffu, a1, off);
        a2 += __shfl_down_sync(0xffffffffu, a2, off);
    }
    if (lane == 0) {
        T5[(size_t)row * 3 + 0] = a0;
        T5[(size_t)row * 3 + 1] = a1;
        T5[(size_t)row * 3 + 2] = a2;
    }
}

// one thread per node, gather 3-wide output
__global__ void k_gather3(const float* __restrict__ T5,
                          const int* __restrict__ rowstart, const int* __restrict__ cnt,
                          const int* __restrict__ csrc, const float* __restrict__ cnrm,
                          const float* __restrict__ dis, const float* __restrict__ b,
                          float* __restrict__ O, int Nn)
{
    int n = blockIdx.x * blockDim.x + threadIdx.x;
    if (n >= Nn) return;
    int base = rowstart[n];
    int deg  = cnt[n];
    float a0 = 0.f, a1 = 0.f, a2 = 0.f;
    for (int j = 0; j < deg; j++) {
        int   s  = __ldg(csrc + base + j);
        float nm = __ldg(cnrm + base + j);
        a0 += __ldg(T5 + (size_t)s * 3 + 0) * nm;
        a1 += __ldg(T5 + (size_t)s * 3 + 1) * nm;
        a2 += __ldg(T5 + (size_t)s * 3 + 2) * nm;
    }
    float d2 = dis[n]; d2 *= d2;
    O[(size_t)n * 3 + 0] = a0 + T5[(size_t)n * 3 + 0] * d2 + b[0];
    O[(size_t)n * 3 + 1] = a1 + T5[(size_t)n * 3 + 1] * d2 + b[1];
    O[(size_t)n * 3 + 2] = a2 + T5[(size_t)n * 3 + 2] * d2 + b[2];
}

// ---------------- launch ----------------
extern "C" void kernel_launch(void* const* d_in, const int* in_sizes, int n_in,
                              void* d_out, int out_size)
{
    const float* x  = (const float*)d_in[0];
    const void*  ei = d_in[1];
    const float* W1 = (const float*)d_in[2];  const float* b1 = (const float*)d_in[3];
    const float* W2 = (const float*)d_in[4];  const float* b2 = (const float*)d_in[5];
    const float* W3 = (const float*)d_in[6];  const float* b3 = (const float*)d_in[7];
    const float* W4 = (const float*)d_in[8];  const float* b4 = (const float*)d_in[9];
    const float* W5 = (const float*)d_in[10]; const float* b5 = (const float*)d_in[11];
    float* out = (float*)d_out;

    int F_IN = in_sizes[2] / HID;          // W1 is [F_IN, 128]
    int N    = in_sizes[0] / F_IN;
    int E    = in_sizes[1] / 2;

    float *dis, *t, *h, *t5, *cnrm;
    int *cnt, *rowstart, *cursor, *bsum, *csrc;
    cudaGetSymbolAddress((void**)&dis, g_dis);
    cudaGetSymbolAddress((void**)&t,   g_t);
    cudaGetSymbolAddress((void**)&h,   g_h);
    cudaGetSymbolAddress((void**)&t5,  g_t5);
    cudaGetSymbolAddress((void**)&cnt, g_cnt);
    cudaGetSymbolAddress((void**)&rowstart, g_rowstart);
    cudaGetSymbolAddress((void**)&cursor,   g_cursor);
    cudaGetSymbolAddress((void**)&bsum,     g_bsum);
    cudaGetSymbolAddress((void**)&csrc,     g_csr_src);
    cudaGetSymbolAddress((void**)&cnrm,     g_csr_nrm);

    int nb = (N + SCAN_B - 1) / SCAN_B;    // scan blocks (<= 1024)

    // ---- dtype probe + CSR build + normalization ----
    k_probe<<<1, 32>>>((const int*)ei, E);
    k_zero2<<<(N + 255) / 256, 256>>>(cnt, cursor, N);
    k_hist <<<(E + 255) / 256, 256>>>(ei, cnt, E);
    k_dis  <<<(N + 255) / 256, 256>>>(cnt, dis, N);
    k_scan_block<<<nb, SCAN_B>>>(cnt, rowstart, bsum, N);
    k_scan_top  <<<1, SCAN_B>>>(bsum, nb);
    k_scan_add  <<<nb, SCAN_B>>>(rowstart, bsum, N);
    k_fill_csr  <<<(E + 255) / 256, 256>>>(ei, rowstart, cursor, dis, csrc, cnrm, E);

    int gemmGrid   = (N + 63) / 64;
    int gatherGrid = (int)(((long long)N * 32 + 255) / 256);

    // ---- layer 1 (no relu on input x) ----
    k_sgemm128 <<<gemmGrid, 256>>>(x, W1, t, N, F_IN, 0);
    k_gather128<<<gatherGrid, 256>>>(t, rowstart, cnt, csrc, cnrm, dis, b1, h, N);

    // ---- layers 2-4 (relu fused into GEMM A-load) ----
    const float* Wmid[3] = {W2, W3, W4};
    const float* bmid[3] = {b2, b3, b4};
    for (int l = 0; l < 3; l++) {
        k_sgemm128 <<<gemmGrid, 256>>>(h, Wmid[l], t, N, HID, 1);
        k_gather128<<<gatherGrid, 256>>>(t, rowstart, cnt, csrc, cnrm, dis, bmid[l], h, N);
    }

    // ---- layer 5 (out = 3, write straight into d_out) ----
    k_gemm3  <<<(int)(((long long)N * 32 + 255) / 256), 256>>>(h, W5, t5, N);
    k_gather3<<<(N + 255) / 256, 256>>>(t5, rowstart, cnt, csrc, cnrm, dis, b5, out, N);
}